// round 2
// baseline (speedup 1.0000x reference)
#include <cuda_runtime.h>

#define D       512
#define NCLS    9
#define EPSF    1e-5f
#define E_PAD   150016   // 150000 padded to multiple of 128

// ---------------- scratch (bss, zero-initialized; no runtime allocation) ----
__device__ float g_h0[(size_t)E_PAD * D];   // LN output / layer-2 output (reused)
__device__ float g_h1[(size_t)E_PAD * D];   // layer-1 output
__device__ float g_sum[D];
__device__ float g_sumsq[D];
__device__ float g_sc[D];
__device__ float g_sh[D];

// ---------------- 1) gather + add + LayerNorm ------------------------------
__global__ void gather_ln(const float* __restrict__ x,
                          const int* __restrict__ src,
                          const int* __restrict__ dst,
                          const float* __restrict__ lnw,
                          float* __restrict__ out, int E)
{
    __shared__ float sred[32];
    __shared__ float sbc;
    const int e = blockIdx.x;
    const int t = threadIdx.x;          // 128 threads, 4 floats each
    const size_t so = (size_t)src[e] * D;
    const size_t dofs = (size_t)dst[e] * D;

    float4 a = *(const float4*)(x + so + t * 4);
    float4 b = *(const float4*)(x + dofs + t * 4);
    float4 v = make_float4(a.x + b.x, a.y + b.y, a.z + b.z, a.w + b.w);

    const int lane = t & 31, wid = t >> 5;

    // mean
    float s = v.x + v.y + v.z + v.w;
    #pragma unroll
    for (int o = 16; o; o >>= 1) s += __shfl_down_sync(0xffffffffu, s, o);
    if (lane == 0) sred[wid] = s;
    __syncthreads();
    if (t == 0) sbc = (sred[0] + sred[1] + sred[2] + sred[3]) * (1.0f / D);
    __syncthreads();
    const float mu = sbc;

    float dx = v.x - mu, dy = v.y - mu, dz = v.z - mu, dw = v.w - mu;
    float ss = dx * dx + dy * dy + dz * dz + dw * dw;
    __syncthreads();            // protect sred reuse
    #pragma unroll
    for (int o = 16; o; o >>= 1) ss += __shfl_down_sync(0xffffffffu, ss, o);
    if (lane == 0) sred[wid] = ss;
    __syncthreads();
    if (t == 0) sbc = rsqrtf((sred[0] + sred[1] + sred[2] + sred[3]) * (1.0f / D) + EPSF);
    __syncthreads();
    const float rs = sbc;

    float4 w = *(const float4*)(lnw + t * 4);
    float4 o4 = make_float4(dx * rs * w.x, dy * rs * w.y, dz * rs * w.z, dw * rs * w.w);
    *(float4*)(out + (size_t)e * D + t * 4) = o4;
}

// ---------------- 2) fp32 tiled GEMM:  C[M,512] = A[M,512] @ W[512,512]^T ---
// Optionally applies BN+ReLU (y = relu(a*sc+sh)) to A elements on load.
template <bool BNRELU>
__global__ void __launch_bounds__(256, 2)
sgemm128(const float* __restrict__ A, const float* __restrict__ W,
         float* __restrict__ C, int Mvalid)
{
    __shared__ float As[8][128];
    __shared__ float Bs[8][128];

    const int tid = threadIdx.x;
    const int tx = tid & 15;        // 0..15  (N direction)
    const int ty = tid >> 4;        // 0..15  (M direction)
    const int rowBase = blockIdx.y * 128;
    const int colBase = blockIdx.x * 128;
    const int lr = tid >> 1;        // 0..127 row within tile
    const int ls = (tid & 1) << 2;  // 0 or 4 (k offset)

    const float* Ap = A + (size_t)(rowBase + lr) * D + ls;
    const float* Wp = W + (size_t)(colBase + lr) * D + ls;

    float acc[8][8];
    #pragma unroll
    for (int i = 0; i < 8; i++)
        #pragma unroll
        for (int j = 0; j < 8; j++) acc[i][j] = 0.0f;

    for (int k0 = 0; k0 < D; k0 += 8) {
        float4 av = *(const float4*)(Ap + k0);
        float4 bv = *(const float4*)(Wp + k0);
        if (BNRELU) {
            float4 s4 = *(const float4*)(g_sc + k0 + ls);
            float4 h4 = *(const float4*)(g_sh + k0 + ls);
            av.x = fmaxf(fmaf(av.x, s4.x, h4.x), 0.0f);
            av.y = fmaxf(fmaf(av.y, s4.y, h4.y), 0.0f);
            av.z = fmaxf(fmaf(av.z, s4.z, h4.z), 0.0f);
            av.w = fmaxf(fmaf(av.w, s4.w, h4.w), 0.0f);
        }
        __syncthreads();                 // previous compute done
        As[ls + 0][lr] = av.x; As[ls + 1][lr] = av.y;
        As[ls + 2][lr] = av.z; As[ls + 3][lr] = av.w;
        Bs[ls + 0][lr] = bv.x; Bs[ls + 1][lr] = bv.y;
        Bs[ls + 2][lr] = bv.z; Bs[ls + 3][lr] = bv.w;
        __syncthreads();

        #pragma unroll
        for (int k = 0; k < 8; k++) {
            float ar[8], br[8];
            *(float4*)&ar[0] = *(const float4*)&As[k][ty * 8];
            *(float4*)&ar[4] = *(const float4*)&As[k][ty * 8 + 4];
            *(float4*)&br[0] = *(const float4*)&Bs[k][tx * 8];
            *(float4*)&br[4] = *(const float4*)&Bs[k][tx * 8 + 4];
            #pragma unroll
            for (int i = 0; i < 8; i++)
                #pragma unroll
                for (int j = 0; j < 8; j++)
                    acc[i][j] = fmaf(ar[i], br[j], acc[i][j]);
        }
    }

    #pragma unroll
    for (int i = 0; i < 8; i++) {
        const int r = rowBase + ty * 8 + i;
        if (r < Mvalid) {
            float* cp = C + (size_t)r * D + colBase + tx * 8;
            *(float4*)cp       = make_float4(acc[i][0], acc[i][1], acc[i][2], acc[i][3]);
            *(float4*)(cp + 4) = make_float4(acc[i][4], acc[i][5], acc[i][6], acc[i][7]);
        }
    }
}

// ---------------- 3) column stats (sum, sumsq over batch) ------------------
__global__ void zero_stats()
{
    const int c = threadIdx.x;
    g_sum[c] = 0.0f;
    g_sumsq[c] = 0.0f;
}

__global__ void colstats(const float* __restrict__ H, int E)
{
    const int c = threadIdx.x;          // 512 threads = one feature each
    const int stride = gridDim.x;
    float s0 = 0.f, s1 = 0.f, q0 = 0.f, q1 = 0.f;
    int r = blockIdx.x;
    for (; r + stride < E; r += 2 * stride) {
        float v0 = H[(size_t)r * D + c];
        float v1 = H[(size_t)(r + stride) * D + c];
        s0 += v0; q0 = fmaf(v0, v0, q0);
        s1 += v1; q1 = fmaf(v1, v1, q1);
    }
    for (; r < E; r += stride) {
        float v = H[(size_t)r * D + c];
        s0 += v; q0 = fmaf(v, v, q0);
    }
    atomicAdd(&g_sum[c], s0 + s1);
    atomicAdd(&g_sumsq[c], q0 + q1);
}

__global__ void finalize_stats(const float* __restrict__ g,
                               const float* __restrict__ b, float invE)
{
    const int c = threadIdx.x;
    const float mean = g_sum[c] * invE;
    const float var  = g_sumsq[c] * invE - mean * mean;
    const float istd = rsqrtf(var + EPSF);
    const float scv  = istd * g[c];
    g_sc[c] = scv;
    g_sh[c] = fmaf(-mean, scv, b[c]);
}

// ---------------- 4) head: out[E,9] = relu(BN(H)) @ Wout^T -----------------
__global__ void head(const float* __restrict__ H,
                     const float* __restrict__ Wout,
                     float* __restrict__ out, int E)
{
    __shared__ float Ws[NCLS * D];
    for (int i = threadIdx.x; i < NCLS * D; i += blockDim.x) Ws[i] = Wout[i];
    __syncthreads();

    const int warp = threadIdx.x >> 5, lane = threadIdx.x & 31;
    const int row = blockIdx.x * 8 + warp;
    if (row >= E) return;

    const float* hp = H + (size_t)row * D;
    float acc[NCLS];
    #pragma unroll
    for (int j = 0; j < NCLS; j++) acc[j] = 0.0f;

    #pragma unroll
    for (int i = 0; i < D / 32; i++) {
        const int k = lane + i * 32;
        const float v = fmaxf(fmaf(hp[k], g_sc[k], g_sh[k]), 0.0f);
        #pragma unroll
        for (int j = 0; j < NCLS; j++) acc[j] = fmaf(v, Ws[j * D + k], acc[j]);
    }
    #pragma unroll
    for (int j = 0; j < NCLS; j++)
        #pragma unroll
        for (int o = 16; o; o >>= 1)
            acc[j] += __shfl_down_sync(0xffffffffu, acc[j], o);

    if (lane == 0) {
        #pragma unroll
        for (int j = 0; j < NCLS; j++) out[(size_t)row * NCLS + j] = acc[j];
    }
}

// ---------------- launch ---------------------------------------------------
extern "C" void kernel_launch(void* const* d_in, const int* in_sizes, int n_in,
                              void* d_out, int out_size)
{
    const float* x    = (const float*)d_in[0];
    const int*   src  = (const int*)d_in[1];
    const int*   dst  = (const int*)d_in[2];
    const float* lnw  = (const float*)d_in[3];
    const float* W1   = (const float*)d_in[4];
    const float* g1   = (const float*)d_in[5];
    const float* b1   = (const float*)d_in[6];
    const float* W2   = (const float*)d_in[7];
    const float* g2   = (const float*)d_in[8];
    const float* b2   = (const float*)d_in[9];
    const float* Wout = (const float*)d_in[10];
    float* out = (float*)d_out;

    const int E = in_sizes[1];
    const float invE = 1.0f / (float)E;
    const int mtiles = (E + 127) / 128;

    float *h0, *h1;
    cudaGetSymbolAddress((void**)&h0, g_h0);
    cudaGetSymbolAddress((void**)&h1, g_h1);

    // 1) gather + LN -> h0
    gather_ln<<<E, 128>>>(x, src, dst, lnw, h0, E);

    // 2) GEMM1: h1 = h0 @ W1^T ; then BN1 stats
    sgemm128<false><<<dim3(D / 128, mtiles), 256>>>(h0, W1, h1, E);
    zero_stats<<<1, D>>>();
    colstats<<<512, D>>>(h1, E);
    finalize_stats<<<1, D>>>(g1, b1, invE);

    // 3) GEMM2: h0 = relu(BN1(h1)) @ W2^T ; then BN2 stats
    sgemm128<true><<<dim3(D / 128, mtiles), 256>>>(h1, W2, h0, E);
    zero_stats<<<1, D>>>();
    colstats<<<512, D>>>(h0, E);
    finalize_stats<<<1, D>>>(g2, b2, invE);

    // 4) head: out = relu(BN2(h0)) @ Wout^T
    head<<<(E + 7) / 8, 256>>>(h0, Wout, out, E);
}

// round 3
// speedup vs baseline: 1.0002x; 1.0002x over previous
#include <cuda_runtime.h>

#define D       512
#define NCLS    9
#define EPSF    1e-5f
#define E_PAD   150016   // 150000 padded to multiple of 128

// ---------------- scratch (bss, zero-initialized; no runtime allocation) ----
__device__ float g_h0[(size_t)E_PAD * D];   // LN output / layer-2 output (reused)
__device__ float g_h1[(size_t)E_PAD * D];   // layer-1 output
__device__ float g_sum[D];
__device__ float g_sumsq[D];
__device__ float g_sc[D];
__device__ float g_sh[D];

// ---------------- 1) gather + add + LayerNorm ------------------------------
__global__ void gather_ln(const float* __restrict__ x,
                          const int* __restrict__ src,
                          const int* __restrict__ dst,
                          const float* __restrict__ lnw,
                          float* __restrict__ out, int E)
{
    __shared__ float sred[32];
    __shared__ float sbc;
    const int e = blockIdx.x;
    const int t = threadIdx.x;          // 128 threads, 4 floats each
    const size_t so = (size_t)src[e] * D;
    const size_t dofs = (size_t)dst[e] * D;

    float4 a = *(const float4*)(x + so + t * 4);
    float4 b = *(const float4*)(x + dofs + t * 4);
    float4 v = make_float4(a.x + b.x, a.y + b.y, a.z + b.z, a.w + b.w);

    const int lane = t & 31, wid = t >> 5;

    // mean
    float s = v.x + v.y + v.z + v.w;
    #pragma unroll
    for (int o = 16; o; o >>= 1) s += __shfl_down_sync(0xffffffffu, s, o);
    if (lane == 0) sred[wid] = s;
    __syncthreads();
    if (t == 0) sbc = (sred[0] + sred[1] + sred[2] + sred[3]) * (1.0f / D);
    __syncthreads();
    const float mu = sbc;

    float dx = v.x - mu, dy = v.y - mu, dz = v.z - mu, dw = v.w - mu;
    float ss = dx * dx + dy * dy + dz * dz + dw * dw;
    __syncthreads();            // protect sred reuse
    #pragma unroll
    for (int o = 16; o; o >>= 1) ss += __shfl_down_sync(0xffffffffu, ss, o);
    if (lane == 0) sred[wid] = ss;
    __syncthreads();
    if (t == 0) sbc = rsqrtf((sred[0] + sred[1] + sred[2] + sred[3]) * (1.0f / D) + EPSF);
    __syncthreads();
    const float rs = sbc;

    float4 w = *(const float4*)(lnw + t * 4);
    float4 o4 = make_float4(dx * rs * w.x, dy * rs * w.y, dz * rs * w.z, dw * rs * w.w);
    *(float4*)(out + (size_t)e * D + t * 4) = o4;
}

// ---------------- 2) fp32 tiled GEMM:  C[M,512] = A[M,512] @ W[512,512]^T ---
// Optionally applies BN+ReLU (y = relu(a*sc+sh)) to A elements on load.
template <bool BNRELU>
__global__ void __launch_bounds__(256, 2)
sgemm128(const float* __restrict__ A, const float* __restrict__ W,
         float* __restrict__ C, int Mvalid)
{
    __shared__ float As[8][128];
    __shared__ float Bs[8][128];

    const int tid = threadIdx.x;
    const int tx = tid & 15;        // 0..15  (N direction)
    const int ty = tid >> 4;        // 0..15  (M direction)
    const int rowBase = blockIdx.y * 128;
    const int colBase = blockIdx.x * 128;
    const int lr = tid >> 1;        // 0..127 row within tile
    const int ls = (tid & 1) << 2;  // 0 or 4 (k offset)

    const float* Ap = A + (size_t)(rowBase + lr) * D + ls;
    const float* Wp = W + (size_t)(colBase + lr) * D + ls;

    float acc[8][8];
    #pragma unroll
    for (int i = 0; i < 8; i++)
        #pragma unroll
        for (int j = 0; j < 8; j++) acc[i][j] = 0.0f;

    for (int k0 = 0; k0 < D; k0 += 8) {
        float4 av = *(const float4*)(Ap + k0);
        float4 bv = *(const float4*)(Wp + k0);
        if (BNRELU) {
            float4 s4 = *(const float4*)(g_sc + k0 + ls);
            float4 h4 = *(const float4*)(g_sh + k0 + ls);
            av.x = fmaxf(fmaf(av.x, s4.x, h4.x), 0.0f);
            av.y = fmaxf(fmaf(av.y, s4.y, h4.y), 0.0f);
            av.z = fmaxf(fmaf(av.z, s4.z, h4.z), 0.0f);
            av.w = fmaxf(fmaf(av.w, s4.w, h4.w), 0.0f);
        }
        __syncthreads();                 // previous compute done
        As[ls + 0][lr] = av.x; As[ls + 1][lr] = av.y;
        As[ls + 2][lr] = av.z; As[ls + 3][lr] = av.w;
        Bs[ls + 0][lr] = bv.x; Bs[ls + 1][lr] = bv.y;
        Bs[ls + 2][lr] = bv.z; Bs[ls + 3][lr] = bv.w;
        __syncthreads();

        #pragma unroll
        for (int k = 0; k < 8; k++) {
            float ar[8], br[8];
            *(float4*)&ar[0] = *(const float4*)&As[k][ty * 8];
            *(float4*)&ar[4] = *(const float4*)&As[k][ty * 8 + 4];
            *(float4*)&br[0] = *(const float4*)&Bs[k][tx * 8];
            *(float4*)&br[4] = *(const float4*)&Bs[k][tx * 8 + 4];
            #pragma unroll
            for (int i = 0; i < 8; i++)
                #pragma unroll
                for (int j = 0; j < 8; j++)
                    acc[i][j] = fmaf(ar[i], br[j], acc[i][j]);
        }
    }

    #pragma unroll
    for (int i = 0; i < 8; i++) {
        const int r = rowBase + ty * 8 + i;
        if (r < Mvalid) {
            float* cp = C + (size_t)r * D + colBase + tx * 8;
            *(float4*)cp       = make_float4(acc[i][0], acc[i][1], acc[i][2], acc[i][3]);
            *(float4*)(cp + 4) = make_float4(acc[i][4], acc[i][5], acc[i][6], acc[i][7]);
        }
    }
}

// ---------------- 3) column stats (sum, sumsq over batch) ------------------
__global__ void zero_stats()
{
    const int c = threadIdx.x;
    g_sum[c] = 0.0f;
    g_sumsq[c] = 0.0f;
}

__global__ void colstats(const float* __restrict__ H, int E)
{
    const int c = threadIdx.x;          // 512 threads = one feature each
    const int stride = gridDim.x;
    float s0 = 0.f, s1 = 0.f, q0 = 0.f, q1 = 0.f;
    int r = blockIdx.x;
    for (; r + stride < E; r += 2 * stride) {
        float v0 = H[(size_t)r * D + c];
        float v1 = H[(size_t)(r + stride) * D + c];
        s0 += v0; q0 = fmaf(v0, v0, q0);
        s1 += v1; q1 = fmaf(v1, v1, q1);
    }
    for (; r < E; r += stride) {
        float v = H[(size_t)r * D + c];
        s0 += v; q0 = fmaf(v, v, q0);
    }
    atomicAdd(&g_sum[c], s0 + s1);
    atomicAdd(&g_sumsq[c], q0 + q1);
}

__global__ void finalize_stats(const float* __restrict__ g,
                               const float* __restrict__ b, float invE)
{
    const int c = threadIdx.x;
    const float mean = g_sum[c] * invE;
    const float var  = g_sumsq[c] * invE - mean * mean;
    const float istd = rsqrtf(var + EPSF);
    const float scv  = istd * g[c];
    g_sc[c] = scv;
    g_sh[c] = fmaf(-mean, scv, b[c]);
}

// ---------------- 4) head: out[E,9] = relu(BN(H)) @ Wout^T -----------------
__global__ void head(const float* __restrict__ H,
                     const float* __restrict__ Wout,
                     float* __restrict__ out, int E)
{
    __shared__ float Ws[NCLS * D];
    for (int i = threadIdx.x; i < NCLS * D; i += blockDim.x) Ws[i] = Wout[i];
    __syncthreads();

    const int warp = threadIdx.x >> 5, lane = threadIdx.x & 31;
    const int row = blockIdx.x * 8 + warp;
    if (row >= E) return;

    const float* hp = H + (size_t)row * D;
    float acc[NCLS];
    #pragma unroll
    for (int j = 0; j < NCLS; j++) acc[j] = 0.0f;

    #pragma unroll
    for (int i = 0; i < D / 32; i++) {
        const int k = lane + i * 32;
        const float v = fmaxf(fmaf(hp[k], g_sc[k], g_sh[k]), 0.0f);
        #pragma unroll
        for (int j = 0; j < NCLS; j++) acc[j] = fmaf(v, Ws[j * D + k], acc[j]);
    }
    #pragma unroll
    for (int j = 0; j < NCLS; j++)
        #pragma unroll
        for (int o = 16; o; o >>= 1)
            acc[j] += __shfl_down_sync(0xffffffffu, acc[j], o);

    if (lane == 0) {
        #pragma unroll
        for (int j = 0; j < NCLS; j++) out[(size_t)row * NCLS + j] = acc[j];
    }
}

// ---------------- launch ---------------------------------------------------
extern "C" void kernel_launch(void* const* d_in, const int* in_sizes, int n_in,
                              void* d_out, int out_size)
{
    const float* x    = (const float*)d_in[0];
    const int*   src  = (const int*)d_in[1];
    const int*   dst  = (const int*)d_in[2];
    const float* lnw  = (const float*)d_in[3];
    const float* W1   = (const float*)d_in[4];
    const float* g1   = (const float*)d_in[5];
    const float* b1   = (const float*)d_in[6];
    const float* W2   = (const float*)d_in[7];
    const float* g2   = (const float*)d_in[8];
    const float* b2   = (const float*)d_in[9];
    const float* Wout = (const float*)d_in[10];
    float* out = (float*)d_out;

    const int E = in_sizes[1];
    const float invE = 1.0f / (float)E;
    const int mtiles = (E + 127) / 128;

    float *h0, *h1;
    cudaGetSymbolAddress((void**)&h0, g_h0);
    cudaGetSymbolAddress((void**)&h1, g_h1);

    // 1) gather + LN -> h0
    gather_ln<<<E, 128>>>(x, src, dst, lnw, h0, E);

    // 2) GEMM1: h1 = h0 @ W1^T ; then BN1 stats
    sgemm128<false><<<dim3(D / 128, mtiles), 256>>>(h0, W1, h1, E);
    zero_stats<<<1, D>>>();
    colstats<<<512, D>>>(h1, E);
    finalize_stats<<<1, D>>>(g1, b1, invE);

    // 3) GEMM2: h0 = relu(BN1(h1)) @ W2^T ; then BN2 stats
    sgemm128<true><<<dim3(D / 128, mtiles), 256>>>(h1, W2, h0, E);
    zero_stats<<<1, D>>>();
    colstats<<<512, D>>>(h0, E);
    finalize_stats<<<1, D>>>(g2, b2, invE);

    // 4) head: out = relu(BN2(h0)) @ Wout^T
    head<<<(E + 7) / 8, 256>>>(h0, Wout, out, E);
}

// round 5
// speedup vs baseline: 2.0334x; 2.0329x over previous
#include <cuda_runtime.h>
#include <cuda_bf16.h>
#include <cstdint>

#define D       512
#define NCLS    9
#define EPSF    1e-5f
#define E_PAD   150016   // 150000 padded to multiple of 128
#define CHUNKS  24       // 8 k-blocks x 3 split-products

// ---------------- scratch (bss; no runtime allocation) ---------------------
__device__ __align__(128) __nv_bfloat16 g_a[(size_t)E_PAD * 1024];   // A hi|lo
__device__ float g_h[(size_t)E_PAD * D];                             // GEMM fp32 out
__device__ __align__(128) __nv_bfloat16 g_w1p[512 * 1024];           // W1 hi|lo
__device__ __align__(128) __nv_bfloat16 g_w2p[512 * 1024];           // W2 hi|lo
__device__ float g_sum[D];
__device__ float g_sumsq[D];
__device__ float g_sc[D];
__device__ float g_sh[D];

// ======================= PTX helpers (sm_100-safe) ==========================
__device__ __forceinline__ uint32_t smem_to_u32(const void* p) {
    uint32_t a;
    asm("{ .reg .u64 t; cvta.to.shared.u64 t, %1; cvt.u32.u64 %0, t; }" : "=r"(a) : "l"(p));
    return a;
}
#define CP_ASYNC16(dst, src) \
    asm volatile("cp.async.cg.shared.global [%0], [%1], 16;" :: "r"(dst), "l"(src) : "memory")
#define CP_COMMIT() asm volatile("cp.async.commit_group;" ::: "memory")
#define LDM_X4(r, addr) \
    asm volatile("ldmatrix.sync.aligned.m8n8.x4.shared.b16 {%0,%1,%2,%3}, [%4];" \
        : "=r"((r)[0]), "=r"((r)[1]), "=r"((r)[2]), "=r"((r)[3]) : "r"(addr))
#define MMA_BF16(d, a, b0, b1) \
    asm volatile("mma.sync.aligned.m16n8k16.row.col.f32.bf16.bf16.f32 " \
        "{%0,%1,%2,%3}, {%4,%5,%6,%7}, {%8,%9}, {%0,%1,%2,%3};" \
        : "+f"((d)[0]), "+f"((d)[1]), "+f"((d)[2]), "+f"((d)[3]) \
        : "r"((a)[0]), "r"((a)[1]), "r"((a)[2]), "r"((a)[3]), "r"(b0), "r"(b1))

// ---------------- 1) gather + add + LayerNorm -> bf16 hi|lo ----------------
__global__ void gather_ln(const float* __restrict__ x,
                          const int* __restrict__ src,
                          const int* __restrict__ dst,
                          const float* __restrict__ lnw,
                          __nv_bfloat16* __restrict__ A, int E)
{
    __shared__ float sred[32];
    __shared__ float sbc;
    const int e = blockIdx.x;
    const int t = threadIdx.x;          // 128 threads, 4 floats each
    const size_t so = (size_t)src[e] * D;
    const size_t dofs = (size_t)dst[e] * D;

    float4 a = *(const float4*)(x + so + t * 4);
    float4 b = *(const float4*)(x + dofs + t * 4);
    float4 v = make_float4(a.x + b.x, a.y + b.y, a.z + b.z, a.w + b.w);

    const int lane = t & 31, wid = t >> 5;

    float s = v.x + v.y + v.z + v.w;
    #pragma unroll
    for (int o = 16; o; o >>= 1) s += __shfl_down_sync(0xffffffffu, s, o);
    if (lane == 0) sred[wid] = s;
    __syncthreads();
    if (t == 0) sbc = (sred[0] + sred[1] + sred[2] + sred[3]) * (1.0f / D);
    __syncthreads();
    const float mu = sbc;

    float dx = v.x - mu, dy = v.y - mu, dz = v.z - mu, dw = v.w - mu;
    float ss = dx * dx + dy * dy + dz * dz + dw * dw;
    __syncthreads();
    #pragma unroll
    for (int o = 16; o; o >>= 1) ss += __shfl_down_sync(0xffffffffu, ss, o);
    if (lane == 0) sred[wid] = ss;
    __syncthreads();
    if (t == 0) sbc = rsqrtf((sred[0] + sred[1] + sred[2] + sred[3]) * (1.0f / D) + EPSF);
    __syncthreads();
    const float rs = sbc;

    float4 w = *(const float4*)(lnw + t * 4);
    float vals[4] = { dx * rs * w.x, dy * rs * w.y, dz * rs * w.z, dw * rs * w.w };

    union { __nv_bfloat16 b[4]; uint2 u; } ph_, pl_;
    #pragma unroll
    for (int m = 0; m < 4; m++) {
        __nv_bfloat16 hi = __float2bfloat16(vals[m]);
        ph_.b[m] = hi;
        pl_.b[m] = __float2bfloat16(vals[m] - __bfloat162float(hi));
    }
    __nv_bfloat16* arow = A + (size_t)e * 1024;
    *(uint2*)(arow + 4 * t)       = ph_.u;
    *(uint2*)(arow + 512 + 4 * t) = pl_.u;
}

// ---------------- weight split: W[512,512] fp32 -> [512][1024] hi|lo -------
__global__ void wsplit(const float* __restrict__ W, __nv_bfloat16* __restrict__ Wp)
{
    const int idx = blockIdx.x * blockDim.x + threadIdx.x;   // 512*512 threads
    const int n = idx >> 9, k = idx & 511;
    float w = W[idx];
    __nv_bfloat16 hi = __float2bfloat16(w);
    __nv_bfloat16 lo = __float2bfloat16(w - __bfloat162float(hi));
    Wp[(size_t)n * 1024 + k]       = hi;
    Wp[(size_t)n * 1024 + 512 + k] = lo;
}

// ---------------- BN+ReLU apply + re-split for next GEMM ------------------
__global__ void bn_split(const float* __restrict__ H, __nv_bfloat16* __restrict__ A, int E)
{
    const int idx = blockIdx.x * blockDim.x + threadIdx.x;   // E*128 threads
    if (idx >= E * 128) return;
    const int r = idx >> 7;
    const int c = (idx & 127) * 4;
    float4 v = *(const float4*)(H + (size_t)r * D + c);
    float4 s4 = *(const float4*)(g_sc + c);
    float4 h4 = *(const float4*)(g_sh + c);
    float vals[4] = {
        fmaxf(fmaf(v.x, s4.x, h4.x), 0.0f), fmaxf(fmaf(v.y, s4.y, h4.y), 0.0f),
        fmaxf(fmaf(v.z, s4.z, h4.z), 0.0f), fmaxf(fmaf(v.w, s4.w, h4.w), 0.0f) };
    union { __nv_bfloat16 b[4]; uint2 u; } ph_, pl_;
    #pragma unroll
    for (int m = 0; m < 4; m++) {
        __nv_bfloat16 hi = __float2bfloat16(vals[m]);
        ph_.b[m] = hi;
        pl_.b[m] = __float2bfloat16(vals[m] - __bfloat162float(hi));
    }
    __nv_bfloat16* arow = A + (size_t)r * 1024;
    *(uint2*)(arow + c)       = ph_.u;
    *(uint2*)(arow + 512 + c) = pl_.u;
}

// ---------------- mma.sync GEMM: C[M,512] = (Ahi+Alo) @ (Whi+Wlo)^T --------
// A [E][1024] bf16 hi|lo, W' [512][1024] bf16 hi|lo.
// 24 chunks of K=64: (hi,hi), (hi,lo), (lo,hi) per k-block j=0..7.
// CTA 128x128, 8 warps (4M x 2N), warp 32x64, 2-stage cp.async pipeline.
#define GEMM_SMEM (2 * 32768)

__global__ void __launch_bounds__(256, 2)
bgemm(const __nv_bfloat16* __restrict__ A, const __nv_bfloat16* __restrict__ W,
      float* __restrict__ C, int E)
{
    extern __shared__ __align__(128) char smem[];
    const int tid = threadIdx.x;
    const int lane = tid & 31, wid = tid >> 5;
    const int m0 = blockIdx.y * 128;
    const int n0 = blockIdx.x * 128;
    const uint32_t sbase = smem_to_u32(smem);

    // ---- cp.async mapping: thread -> (row = tid/2, 4 groups of 16B) ----
    const int lrow = tid >> 1;
    const int lg0  = (tid & 1) * 4;
    const __nv_bfloat16* Abase = A + (size_t)(m0 + lrow) * 1024 + lg0 * 8;
    const __nv_bfloat16* Wbase = W + (size_t)(n0 + lrow) * 1024 + lg0 * 8;
    uint32_t dsw[4];
    #pragma unroll
    for (int q = 0; q < 4; q++)
        dsw[q] = (uint32_t)(lrow * 128 + ((lg0 + q) ^ (lrow & 7)) * 16);

    // ---- ldmatrix fragment addresses ----
    const int wm = (wid & 3) * 32;        // warp M offset in tile
    const int wn = (wid >> 2) * 64;       // warp N offset in tile
    const int ar = wm + (lane & 15);                       // A row (+ mf*16)
    const int agsel = lane >> 4;                           // k-group half
    const int br = wn + (lane & 7) + ((lane >> 4) << 3);   // W row (+ np*16)
    const int bgsel = (lane >> 3) & 1;

    float acc[2][8][4];
    #pragma unroll
    for (int i = 0; i < 2; i++)
        #pragma unroll
        for (int j = 0; j < 8; j++)
            #pragma unroll
            for (int q = 0; q < 4; q++) acc[i][j][q] = 0.0f;

    // issue chunk i into buffer buf
    auto issue = [&](int i, int buf) {
        const int j = i / 3, t3 = i - j * 3;
        const int ax = j * 64 + ((t3 == 2) ? 512 : 0);
        const int wx = j * 64 + ((t3 == 1) ? 512 : 0);
        const char* aps = (const char*)(Abase + ax);
        const char* wps = (const char*)(Wbase + wx);
        const uint32_t da = sbase + buf * 32768u;
        const uint32_t dw = da + 16384u;
        #pragma unroll
        for (int q = 0; q < 4; q++) {
            CP_ASYNC16(da + dsw[q], aps + q * 16);
            CP_ASYNC16(dw + dsw[q], wps + q * 16);
        }
        CP_COMMIT();
    };

    issue(0, 0);
    int buf = 0;
    #pragma unroll 1
    for (int i = 0; i < CHUNKS; i++) {
        if (i < CHUNKS - 1) {
            issue(i + 1, buf ^ 1);
            asm volatile("cp.async.wait_group 1;" ::: "memory");
        } else {
            asm volatile("cp.async.wait_group 0;" ::: "memory");
        }
        __syncthreads();

        const uint32_t sA = sbase + buf * 32768u;
        const uint32_t sW = sA + 16384u;
        #pragma unroll
        for (int kk = 0; kk < 4; kk++) {
            const int kg2 = kk * 2;
            uint32_t a[2][4];
            #pragma unroll
            for (int mf = 0; mf < 2; mf++) {
                const int r = ar + mf * 16;
                const int g = kg2 + agsel;
                LDM_X4(a[mf], sA + r * 128 + ((g ^ (r & 7)) * 16));
            }
            #pragma unroll
            for (int np = 0; np < 4; np++) {
                const int r = br + np * 16;
                const int g = kg2 + bgsel;
                uint32_t b[4];
                LDM_X4(b, sW + r * 128 + ((g ^ (r & 7)) * 16));
                #pragma unroll
                for (int mf = 0; mf < 2; mf++) {
                    MMA_BF16(acc[mf][np * 2],     a[mf], b[0], b[1]);
                    MMA_BF16(acc[mf][np * 2 + 1], a[mf], b[2], b[3]);
                }
            }
        }
        __syncthreads();
        buf ^= 1;
    }

    // ---- epilogue: fragment -> global fp32 ----
    const int cq = (lane & 3) * 2;
    const int rq = lane >> 2;
    #pragma unroll
    for (int mf = 0; mf < 2; mf++) {
        const int r0 = m0 + wm + mf * 16 + rq;
        #pragma unroll
        for (int nf = 0; nf < 8; nf++) {
            const int col = n0 + wn + nf * 8 + cq;
            if (r0 < E)
                *(float2*)(C + (size_t)r0 * D + col) =
                    make_float2(acc[mf][nf][0], acc[mf][nf][1]);
            if (r0 + 8 < E)
                *(float2*)(C + (size_t)(r0 + 8) * D + col) =
                    make_float2(acc[mf][nf][2], acc[mf][nf][3]);
        }
    }
}

// ---------------- column stats (sum, sumsq over batch) ---------------------
__global__ void zero_stats()
{
    const int c = threadIdx.x;
    g_sum[c] = 0.0f;
    g_sumsq[c] = 0.0f;
}

__global__ void colstats(const float* __restrict__ H, int E)
{
    const int c = threadIdx.x;
    const int stride = gridDim.x;
    float s0 = 0.f, s1 = 0.f, q0 = 0.f, q1 = 0.f;
    int r = blockIdx.x;
    for (; r + stride < E; r += 2 * stride) {
        float v0 = H[(size_t)r * D + c];
        float v1 = H[(size_t)(r + stride) * D + c];
        s0 += v0; q0 = fmaf(v0, v0, q0);
        s1 += v1; q1 = fmaf(v1, v1, q1);
    }
    for (; r < E; r += stride) {
        float v = H[(size_t)r * D + c];
        s0 += v; q0 = fmaf(v, v, q0);
    }
    atomicAdd(&g_sum[c], s0 + s1);
    atomicAdd(&g_sumsq[c], q0 + q1);
}

__global__ void finalize_stats(const float* __restrict__ g,
                               const float* __restrict__ b, float invE)
{
    const int c = threadIdx.x;
    const float mean = g_sum[c] * invE;
    const float var  = g_sumsq[c] * invE - mean * mean;
    const float istd = rsqrtf(var + EPSF);
    const float scv  = istd * g[c];
    g_sc[c] = scv;
    g_sh[c] = fmaf(-mean, scv, b[c]);
}

// ---------------- head: out[E,9] = relu(BN(H)) @ Wout^T --------------------
__global__ void head(const float* __restrict__ H,
                     const float* __restrict__ Wout,
                     float* __restrict__ out, int E)
{
    __shared__ float Ws[NCLS * D];
    for (int i = threadIdx.x; i < NCLS * D; i += blockDim.x) Ws[i] = Wout[i];
    __syncthreads();

    const int warp = threadIdx.x >> 5, lane = threadIdx.x & 31;
    const int row = blockIdx.x * 8 + warp;
    if (row >= E) return;

    const float* hp = H + (size_t)row * D;
    float acc[NCLS];
    #pragma unroll
    for (int j = 0; j < NCLS; j++) acc[j] = 0.0f;

    #pragma unroll
    for (int i = 0; i < D / 32; i++) {
        const int k = lane + i * 32;
        const float v = fmaxf(fmaf(hp[k], g_sc[k], g_sh[k]), 0.0f);
        #pragma unroll
        for (int j = 0; j < NCLS; j++) acc[j] = fmaf(v, Ws[j * D + k], acc[j]);
    }
    #pragma unroll
    for (int j = 0; j < NCLS; j++)
        #pragma unroll
        for (int o = 16; o; o >>= 1)
            acc[j] += __shfl_down_sync(0xffffffffu, acc[j], o);

    if (lane == 0) {
        #pragma unroll
        for (int j = 0; j < NCLS; j++) out[(size_t)row * NCLS + j] = acc[j];
    }
}

// ---------------- launch ---------------------------------------------------
extern "C" void kernel_launch(void* const* d_in, const int* in_sizes, int n_in,
                              void* d_out, int out_size)
{
    const float* x    = (const float*)d_in[0];
    const int*   src  = (const int*)d_in[1];
    const int*   dst  = (const int*)d_in[2];
    const float* lnw  = (const float*)d_in[3];
    const float* W1   = (const float*)d_in[4];
    const float* g1   = (const float*)d_in[5];
    const float* b1   = (const float*)d_in[6];
    const float* W2   = (const float*)d_in[7];
    const float* g2   = (const float*)d_in[8];
    const float* b2   = (const float*)d_in[9];
    const float* Wout = (const float*)d_in[10];
    float* out = (float*)d_out;

    const int E = in_sizes[1];
    const float invE = 1.0f / (float)E;
    const int mtiles = (E + 127) / 128;

    void *pa, *phb, *pw1, *pw2;
    cudaGetSymbolAddress(&pa, g_a);
    cudaGetSymbolAddress(&phb, g_h);
    cudaGetSymbolAddress(&pw1, g_w1p);
    cudaGetSymbolAddress(&pw2, g_w2p);

    cudaFuncSetAttribute(bgemm, cudaFuncAttributeMaxDynamicSharedMemorySize, GEMM_SMEM);

    float* h = (float*)phb;
    __nv_bfloat16* A = (__nv_bfloat16*)pa;

    // 1) gather + LN -> A (bf16 hi|lo); weight splits
    gather_ln<<<E, 128>>>(x, src, dst, lnw, A, E);
    wsplit<<<512, 512>>>(W1, (__nv_bfloat16*)pw1);
    wsplit<<<512, 512>>>(W2, (__nv_bfloat16*)pw2);

    // 2) GEMM1 (tensor cores): h = A @ W1^T ; BN1 stats
    bgemm<<<dim3(4, mtiles), 256, GEMM_SMEM>>>(A, (__nv_bfloat16*)pw1, h, E);
    zero_stats<<<1, D>>>();
    colstats<<<512, D>>>(h, E);
    finalize_stats<<<1, D>>>(g1, b1, invE);

    // 3) BN1+ReLU apply + re-split -> A ; GEMM2 ; BN2 stats
    bn_split<<<(E * 128 + 255) / 256, 256>>>(h, A, E);
    bgemm<<<dim3(4, mtiles), 256, GEMM_SMEM>>>(A, (__nv_bfloat16*)pw2, h, E);
    zero_stats<<<1, D>>>();
    colstats<<<512, D>>>(h, E);
    finalize_stats<<<1, D>>>(g2, b2, invE);

    // 4) head
    head<<<(E + 7) / 8, 256>>>(h, Wout, out, E);
}

// round 6
// speedup vs baseline: 2.1148x; 1.0401x over previous
#include <cuda_runtime.h>
#include <cuda_bf16.h>
#include <cstdint>

#define D       512
#define NCLS    9
#define EPSF    1e-5f
#define E_PAD   150016   // 150000 padded to multiple of 128
#define CHUNKS  24       // 8 k-blocks x 3 split-products
#define STAGES  3
#define STG_B   32768u

// ---------------- scratch (bss; no runtime allocation) ---------------------
__device__ __align__(128) __nv_bfloat16 g_a[(size_t)E_PAD * 1024];   // A hi|lo
__device__ float g_h[(size_t)E_PAD * D];                             // GEMM fp32 out
__device__ __align__(128) __nv_bfloat16 g_w1p[512 * 1024];           // W1 hi|lo
__device__ __align__(128) __nv_bfloat16 g_w2p[512 * 1024];           // W2 hi|lo
__device__ float g_sum[D];
__device__ float g_sumsq[D];
__device__ float g_sc[D];
__device__ float g_sh[D];

// ======================= PTX helpers (sm_100-safe) ==========================
__device__ __forceinline__ uint32_t smem_to_u32(const void* p) {
    uint32_t a;
    asm("{ .reg .u64 t; cvta.to.shared.u64 t, %1; cvt.u32.u64 %0, t; }" : "=r"(a) : "l"(p));
    return a;
}
#define CP_ASYNC16(dst, src) \
    asm volatile("cp.async.cg.shared.global [%0], [%1], 16;" :: "r"(dst), "l"(src) : "memory")
#define CP_COMMIT() asm volatile("cp.async.commit_group;" ::: "memory")
#define LDM_X4(r, addr) \
    asm volatile("ldmatrix.sync.aligned.m8n8.x4.shared.b16 {%0,%1,%2,%3}, [%4];" \
        : "=r"((r)[0]), "=r"((r)[1]), "=r"((r)[2]), "=r"((r)[3]) : "r"(addr))
#define MMA_BF16(d, a, b0, b1) \
    asm volatile("mma.sync.aligned.m16n8k16.row.col.f32.bf16.bf16.f32 " \
        "{%0,%1,%2,%3}, {%4,%5,%6,%7}, {%8,%9}, {%0,%1,%2,%3};" \
        : "+f"((d)[0]), "+f"((d)[1]), "+f"((d)[2]), "+f"((d)[3]) \
        : "r"((a)[0]), "r"((a)[1]), "r"((a)[2]), "r"((a)[3]), "r"(b0), "r"(b1))

// ---------------- 1) gather + add + LayerNorm -> bf16 hi|lo ----------------
__global__ void gather_ln(const float* __restrict__ x,
                          const int* __restrict__ src,
                          const int* __restrict__ dst,
                          const float* __restrict__ lnw,
                          __nv_bfloat16* __restrict__ A, int E)
{
    __shared__ float sred[32];
    __shared__ float sbc;
    const int e = blockIdx.x;
    const int t = threadIdx.x;          // 128 threads, 4 floats each
    const size_t so = (size_t)src[e] * D;
    const size_t dofs = (size_t)dst[e] * D;

    float4 a = *(const float4*)(x + so + t * 4);
    float4 b = *(const float4*)(x + dofs + t * 4);
    float4 v = make_float4(a.x + b.x, a.y + b.y, a.z + b.z, a.w + b.w);

    const int lane = t & 31, wid = t >> 5;

    float s = v.x + v.y + v.z + v.w;
    #pragma unroll
    for (int o = 16; o; o >>= 1) s += __shfl_down_sync(0xffffffffu, s, o);
    if (lane == 0) sred[wid] = s;
    __syncthreads();
    if (t == 0) sbc = (sred[0] + sred[1] + sred[2] + sred[3]) * (1.0f / D);
    __syncthreads();
    const float mu = sbc;

    float dx = v.x - mu, dy = v.y - mu, dz = v.z - mu, dw = v.w - mu;
    float ss = dx * dx + dy * dy + dz * dz + dw * dw;
    __syncthreads();
    #pragma unroll
    for (int o = 16; o; o >>= 1) ss += __shfl_down_sync(0xffffffffu, ss, o);
    if (lane == 0) sred[wid] = ss;
    __syncthreads();
    if (t == 0) sbc = rsqrtf((sred[0] + sred[1] + sred[2] + sred[3]) * (1.0f / D) + EPSF);
    __syncthreads();
    const float rs = sbc;

    float4 w = *(const float4*)(lnw + t * 4);
    float vals[4] = { dx * rs * w.x, dy * rs * w.y, dz * rs * w.z, dw * rs * w.w };

    union { __nv_bfloat16 b[4]; uint2 u; } ph_, pl_;
    #pragma unroll
    for (int m = 0; m < 4; m++) {
        __nv_bfloat16 hi = __float2bfloat16(vals[m]);
        ph_.b[m] = hi;
        pl_.b[m] = __float2bfloat16(vals[m] - __bfloat162float(hi));
    }
    __nv_bfloat16* arow = A + (size_t)e * 1024;
    *(uint2*)(arow + 4 * t)       = ph_.u;
    *(uint2*)(arow + 512 + 4 * t) = pl_.u;
}

// ---------------- weight split: W[512,512] fp32 -> [512][1024] hi|lo -------
__global__ void wsplit(const float* __restrict__ W, __nv_bfloat16* __restrict__ Wp)
{
    const int idx = blockIdx.x * blockDim.x + threadIdx.x;   // 512*512 threads
    const int n = idx >> 9, k = idx & 511;
    float w = W[idx];
    __nv_bfloat16 hi = __float2bfloat16(w);
    __nv_bfloat16 lo = __float2bfloat16(w - __bfloat162float(hi));
    Wp[(size_t)n * 1024 + k]       = hi;
    Wp[(size_t)n * 1024 + 512 + k] = lo;
}

// ---------------- BN+ReLU apply + re-split for next GEMM ------------------
__global__ void bn_split(const float* __restrict__ H, __nv_bfloat16* __restrict__ A, int E)
{
    const int idx = blockIdx.x * blockDim.x + threadIdx.x;   // E*128 threads
    if (idx >= E * 128) return;
    const int r = idx >> 7;
    const int c = (idx & 127) * 4;
    float4 v = *(const float4*)(H + (size_t)r * D + c);
    float4 s4 = *(const float4*)(g_sc + c);
    float4 h4 = *(const float4*)(g_sh + c);
    float vals[4] = {
        fmaxf(fmaf(v.x, s4.x, h4.x), 0.0f), fmaxf(fmaf(v.y, s4.y, h4.y), 0.0f),
        fmaxf(fmaf(v.z, s4.z, h4.z), 0.0f), fmaxf(fmaf(v.w, s4.w, h4.w), 0.0f) };
    union { __nv_bfloat16 b[4]; uint2 u; } ph_, pl_;
    #pragma unroll
    for (int m = 0; m < 4; m++) {
        __nv_bfloat16 hi = __float2bfloat16(vals[m]);
        ph_.b[m] = hi;
        pl_.b[m] = __float2bfloat16(vals[m] - __bfloat162float(hi));
    }
    __nv_bfloat16* arow = A + (size_t)r * 1024;
    *(uint2*)(arow + c)       = ph_.u;
    *(uint2*)(arow + 512 + c) = pl_.u;
}

// ---------------- mma.sync GEMM + fused column stats -----------------------
// C[M,512] = (Ahi+Alo) @ (Whi+Wlo)^T ; also atomically accumulates
// per-column sum / sumsq of C into g_sum / g_sumsq.
// 24 chunks of K=64: (hi,hi), (hi,lo), (lo,hi) per k-block j=0..7.
// CTA 128x128, 8 warps (4M x 2N), 3-stage cp.async pipeline, 1 barrier/chunk.
#define GEMM_SMEM (STAGES * 32768)

__global__ void __launch_bounds__(256, 2)
bgemm(const __nv_bfloat16* __restrict__ A, const __nv_bfloat16* __restrict__ W,
      float* __restrict__ C, int E)
{
    extern __shared__ __align__(128) char smem[];
    const int tid = threadIdx.x;
    const int lane = tid & 31, wid = tid >> 5;
    const int m0 = blockIdx.y * 128;
    const int n0 = blockIdx.x * 128;
    const uint32_t sbase = smem_to_u32(smem);

    // ---- cp.async mapping: thread -> (row = tid/2, 4 groups of 16B) ----
    const int lrow = tid >> 1;
    const int lg0  = (tid & 1) * 4;
    const __nv_bfloat16* Abase = A + (size_t)(m0 + lrow) * 1024 + lg0 * 8;
    const __nv_bfloat16* Wbase = W + (size_t)(n0 + lrow) * 1024 + lg0 * 8;
    uint32_t dsw[4];
    #pragma unroll
    for (int q = 0; q < 4; q++)
        dsw[q] = (uint32_t)(lrow * 128 + ((lg0 + q) ^ (lrow & 7)) * 16);

    // ---- ldmatrix fragment addresses ----
    const int wm = (wid & 3) * 32;        // warp M offset in tile
    const int wn = (wid >> 2) * 64;       // warp N offset in tile
    const int ar = wm + (lane & 15);                       // A row (+ mf*16)
    const int agsel = lane >> 4;                           // k-group half
    const int br = wn + (lane & 7) + ((lane >> 4) << 3);   // W row (+ np*16)
    const int bgsel = (lane >> 3) & 1;

    float acc[2][8][4];
    #pragma unroll
    for (int i = 0; i < 2; i++)
        #pragma unroll
        for (int j = 0; j < 8; j++)
            #pragma unroll
            for (int q = 0; q < 4; q++) acc[i][j][q] = 0.0f;

    // issue chunk i into stage st
    auto issue = [&](int i, int st) {
        const int j = i / 3, t3 = i - j * 3;
        const int ax = j * 64 + ((t3 == 2) ? 512 : 0);
        const int wx = j * 64 + ((t3 == 1) ? 512 : 0);
        const char* aps = (const char*)(Abase + ax);
        const char* wps = (const char*)(Wbase + wx);
        const uint32_t da = sbase + st * STG_B;
        const uint32_t dw = da + 16384u;
        #pragma unroll
        for (int q = 0; q < 4; q++) {
            CP_ASYNC16(da + dsw[q], aps + q * 16);
            CP_ASYNC16(dw + dsw[q], wps + q * 16);
        }
        CP_COMMIT();
    };

    auto compute = [&](int st) {
        const uint32_t sA = sbase + st * STG_B;
        const uint32_t sW = sA + 16384u;
        #pragma unroll
        for (int kk = 0; kk < 4; kk++) {
            const int kg2 = kk * 2;
            uint32_t a[2][4];
            #pragma unroll
            for (int mf = 0; mf < 2; mf++) {
                const int r = ar + mf * 16;
                const int g = kg2 + agsel;
                LDM_X4(a[mf], sA + r * 128 + ((g ^ (r & 7)) * 16));
            }
            #pragma unroll
            for (int np = 0; np < 4; np++) {
                const int r = br + np * 16;
                const int g = kg2 + bgsel;
                uint32_t b[4];
                LDM_X4(b, sW + r * 128 + ((g ^ (r & 7)) * 16));
                #pragma unroll
                for (int mf = 0; mf < 2; mf++) {
                    MMA_BF16(acc[mf][np * 2],     a[mf], b[0], b[1]);
                    MMA_BF16(acc[mf][np * 2 + 1], a[mf], b[2], b[3]);
                }
            }
        }
    };

    // ---- 3-stage mainloop: wait -> barrier -> issue(i+2) -> compute(i) ----
    issue(0, 0);
    issue(1, 1);
    #pragma unroll 1
    for (int i = 0; i < CHUNKS; i++) {
        if (i < CHUNKS - 1)
            asm volatile("cp.async.wait_group 1;" ::: "memory");
        else
            asm volatile("cp.async.wait_group 0;" ::: "memory");
        __syncthreads();
        if (i + 2 < CHUNKS) issue(i + 2, (i + 2) % STAGES);
        compute(i % STAGES);
    }

    // ---- epilogue: fragment -> global fp32 ----
    const int cq = (lane & 3) * 2;
    const int rq = lane >> 2;
    #pragma unroll
    for (int mf = 0; mf < 2; mf++) {
        const int r0 = m0 + wm + mf * 16 + rq;
        #pragma unroll
        for (int nf = 0; nf < 8; nf++) {
            const int col = n0 + wn + nf * 8 + cq;
            if (r0 < E)
                *(float2*)(C + (size_t)r0 * D + col) =
                    make_float2(acc[mf][nf][0], acc[mf][nf][1]);
            if (r0 + 8 < E)
                *(float2*)(C + (size_t)(r0 + 8) * D + col) =
                    make_float2(acc[mf][nf][2], acc[mf][nf][3]);
        }
    }

    // ---- fused BN column stats (rows >= E are exactly zero in A) ----------
    float* ssum = (float*)smem;          // 128 floats
    float* ssq  = (float*)smem + 128;    // 128 floats
    __syncthreads();                     // pipeline smem reads all done
    if (tid < 128) { ssum[tid] = 0.0f; ssq[tid] = 0.0f; }
    __syncthreads();

    #pragma unroll
    for (int nf = 0; nf < 8; nf++) {
        #pragma unroll
        for (int p = 0; p < 2; p++) {
            float v0 = acc[0][nf][p],     v1 = acc[0][nf][p + 2];
            float v2 = acc[1][nf][p],     v3 = acc[1][nf][p + 2];
            float s = v0 + v1 + v2 + v3;
            float q = v0 * v0 + v1 * v1 + v2 * v2 + v3 * v3;
            #pragma unroll
            for (int mk = 4; mk <= 16; mk <<= 1) {
                s += __shfl_xor_sync(0xffffffffu, s, mk);
                q += __shfl_xor_sync(0xffffffffu, q, mk);
            }
            if (lane < 4) {
                const int cl = wn + nf * 8 + (lane & 3) * 2 + p;
                atomicAdd(&ssum[cl], s);
                atomicAdd(&ssq[cl], q);
            }
        }
    }
    __syncthreads();
    if (tid < 128) {
        atomicAdd(&g_sum[n0 + tid], ssum[tid]);
        atomicAdd(&g_sumsq[n0 + tid], ssq[tid]);
    }
}

// ---------------- stats setup / finalize -----------------------------------
__global__ void zero_stats()
{
    const int c = threadIdx.x;
    g_sum[c] = 0.0f;
    g_sumsq[c] = 0.0f;
}

__global__ void finalize_stats(const float* __restrict__ g,
                               const float* __restrict__ b, float invE)
{
    const int c = threadIdx.x;
    const float mean = g_sum[c] * invE;
    const float var  = g_sumsq[c] * invE - mean * mean;
    const float istd = rsqrtf(var + EPSF);
    const float scv  = istd * g[c];
    g_sc[c] = scv;
    g_sh[c] = fmaf(-mean, scv, b[c]);
}

// ---------------- head: out[E,9] = relu(BN(H)) @ Wout^T --------------------
__global__ void head(const float* __restrict__ H,
                     const float* __restrict__ Wout,
                     float* __restrict__ out, int E)
{
    __shared__ float Ws[NCLS * D];
    for (int i = threadIdx.x; i < NCLS * D; i += blockDim.x) Ws[i] = Wout[i];
    __syncthreads();

    const int warp = threadIdx.x >> 5, lane = threadIdx.x & 31;
    const int row = blockIdx.x * 8 + warp;
    if (row >= E) return;

    const float* hp = H + (size_t)row * D;
    float acc[NCLS];
    #pragma unroll
    for (int j = 0; j < NCLS; j++) acc[j] = 0.0f;

    #pragma unroll
    for (int i = 0; i < D / 32; i++) {
        const int k = lane + i * 32;
        const float v = fmaxf(fmaf(hp[k], g_sc[k], g_sh[k]), 0.0f);
        #pragma unroll
        for (int j = 0; j < NCLS; j++) acc[j] = fmaf(v, Ws[j * D + k], acc[j]);
    }
    #pragma unroll
    for (int j = 0; j < NCLS; j++)
        #pragma unroll
        for (int o = 16; o; o >>= 1)
            acc[j] += __shfl_down_sync(0xffffffffu, acc[j], o);

    if (lane == 0) {
        #pragma unroll
        for (int j = 0; j < NCLS; j++) out[(size_t)row * NCLS + j] = acc[j];
    }
}

// ---------------- launch ---------------------------------------------------
extern "C" void kernel_launch(void* const* d_in, const int* in_sizes, int n_in,
                              void* d_out, int out_size)
{
    const float* x    = (const float*)d_in[0];
    const int*   src  = (const int*)d_in[1];
    const int*   dst  = (const int*)d_in[2];
    const float* lnw  = (const float*)d_in[3];
    const float* W1   = (const float*)d_in[4];
    const float* g1   = (const float*)d_in[5];
    const float* b1   = (const float*)d_in[6];
    const float* W2   = (const float*)d_in[7];
    const float* g2   = (const float*)d_in[8];
    const float* b2   = (const float*)d_in[9];
    const float* Wout = (const float*)d_in[10];
    float* out = (float*)d_out;

    const int E = in_sizes[1];
    const float invE = 1.0f / (float)E;
    const int mtiles = (E + 127) / 128;

    void *pa, *phb, *pw1, *pw2;
    cudaGetSymbolAddress(&pa, g_a);
    cudaGetSymbolAddress(&phb, g_h);
    cudaGetSymbolAddress(&pw1, g_w1p);
    cudaGetSymbolAddress(&pw2, g_w2p);

    cudaFuncSetAttribute(bgemm, cudaFuncAttributeMaxDynamicSharedMemorySize, GEMM_SMEM);

    float* h = (float*)phb;
    __nv_bfloat16* A = (__nv_bfloat16*)pa;

    // 1) gather + LN -> A (bf16 hi|lo); weight splits
    gather_ln<<<E, 128>>>(x, src, dst, lnw, A, E);
    wsplit<<<512, 512>>>(W1, (__nv_bfloat16*)pw1);
    wsplit<<<512, 512>>>(W2, (__nv_bfloat16*)pw2);

    // 2) GEMM1 (+ fused BN1 stats): h = A @ W1^T
    zero_stats<<<1, D>>>();
    bgemm<<<dim3(4, mtiles), 256, GEMM_SMEM>>>(A, (__nv_bfloat16*)pw1, h, E);
    finalize_stats<<<1, D>>>(g1, b1, invE);

    // 3) BN1+ReLU apply + re-split -> A ; GEMM2 (+ fused BN2 stats)
    bn_split<<<(E * 128 + 255) / 256, 256>>>(h, A, E);
    zero_stats<<<1, D>>>();
    bgemm<<<dim3(4, mtiles), 256, GEMM_SMEM>>>(A, (__nv_bfloat16*)pw2, h, E);
    finalize_stats<<<1, D>>>(g2, b2, invE);

    // 4) head
    head<<<(E + 7) / 8, 256>>>(h, Wout, out, E);
}